// round 3
// baseline (speedup 1.0000x reference)
#include <cuda_runtime.h>
#include <math.h>

#define BATCH   2
#define SEQ     2048
#define DMODEL  1024
#define NHEADS  16
#define HDIM    64
#define BLK     64
#define NB      (SEQ/BLK)         // 32 query blocks per batch
#define MROWS   (BATCH*SEQ)       // 4096
#define APITCH  68                // smem pitch (floats) for attention tiles

// Scratch (device globals: allocation-free, graph-capture safe)
__device__ __align__(16) float g_q[MROWS*DMODEL];
__device__ __align__(16) float g_k[MROWS*DMODEL];
__device__ __align__(16) float g_v[MROWS*DMODEL];
__device__ __align__(16) float g_attn[MROWS*DMODEL];

// ----------------------------------------------------------------------------
// SGEMM: C[M,N] = A[M,K] @ W[K,N] + bias[N]
// 128x128x16 tiles, 256 threads, 8x8 per thread (4+4 split fragments),
// double-buffered shared memory. M,N multiples of 128; K multiple of 16.
// ----------------------------------------------------------------------------
__global__ __launch_bounds__(256, 2)
void sgemm_bias128(const float* __restrict__ A, const float* __restrict__ W,
                   const float* __restrict__ bias, float* __restrict__ C,
                   int M, int N, int K)
{
    __shared__ float As[2][16][132];   // [k][m], padded
    __shared__ float Bs[2][16][132];   // [k][n], padded

    const int tid = threadIdx.x;
    const int tx  = tid & 15;
    const int ty  = tid >> 4;
    const int bm  = blockIdx.y * 128;
    const int bn  = blockIdx.x * 128;

    float acc[8][8];
#pragma unroll
    for (int i = 0; i < 8; i++)
#pragma unroll
        for (int j = 0; j < 8; j++) acc[i][j] = 0.f;

    // A tile: 128 rows x 16 cols = 512 float4 ; thread loads f=tid, tid+256
    const int a_r0 = tid >> 2;
    const int a_c0 = (tid & 3) * 4;
    const int a_r1 = (tid + 256) >> 2;
    // B tile: 16 rows x 128 cols = 512 float4
    const int b_r0 = tid >> 5;
    const int b_c0 = (tid & 31) * 4;
    const int b_r1 = (tid + 256) >> 5;

    const int nkt = K / 16;
    float4 aR0, aR1, bR0, bR1;

    // prologue: tile 0
    aR0 = *(const float4*)&A[(size_t)(bm + a_r0) * K + a_c0];
    aR1 = *(const float4*)&A[(size_t)(bm + a_r1) * K + a_c0];
    bR0 = *(const float4*)&W[(size_t)(b_r0) * N + bn + b_c0];
    bR1 = *(const float4*)&W[(size_t)(b_r1) * N + bn + b_c0];
    As[0][a_c0+0][a_r0] = aR0.x; As[0][a_c0+1][a_r0] = aR0.y;
    As[0][a_c0+2][a_r0] = aR0.z; As[0][a_c0+3][a_r0] = aR0.w;
    As[0][a_c0+0][a_r1] = aR1.x; As[0][a_c0+1][a_r1] = aR1.y;
    As[0][a_c0+2][a_r1] = aR1.z; As[0][a_c0+3][a_r1] = aR1.w;
    *(float4*)&Bs[0][b_r0][b_c0] = bR0;
    *(float4*)&Bs[0][b_r1][b_c0] = bR1;
    __syncthreads();

    for (int kt = 0; kt < nkt; kt++) {
        const int buf = kt & 1;
        if (kt + 1 < nkt) {
            const int ko = (kt + 1) * 16;
            aR0 = *(const float4*)&A[(size_t)(bm + a_r0) * K + ko + a_c0];
            aR1 = *(const float4*)&A[(size_t)(bm + a_r1) * K + ko + a_c0];
            bR0 = *(const float4*)&W[(size_t)(ko + b_r0) * N + bn + b_c0];
            bR1 = *(const float4*)&W[(size_t)(ko + b_r1) * N + bn + b_c0];
        }
#pragma unroll
        for (int k = 0; k < 16; k++) {
            float4 a0 = *(const float4*)&As[buf][k][ty * 4];
            float4 a1 = *(const float4*)&As[buf][k][64 + ty * 4];
            float4 b0 = *(const float4*)&Bs[buf][k][tx * 4];
            float4 b1 = *(const float4*)&Bs[buf][k][64 + tx * 4];
            float av[8] = {a0.x, a0.y, a0.z, a0.w, a1.x, a1.y, a1.z, a1.w};
            float bv[8] = {b0.x, b0.y, b0.z, b0.w, b1.x, b1.y, b1.z, b1.w};
#pragma unroll
            for (int i = 0; i < 8; i++)
#pragma unroll
                for (int j = 0; j < 8; j++)
                    acc[i][j] = fmaf(av[i], bv[j], acc[i][j]);
        }
        if (kt + 1 < nkt) {
            const int nb2 = buf ^ 1;
            As[nb2][a_c0+0][a_r0] = aR0.x; As[nb2][a_c0+1][a_r0] = aR0.y;
            As[nb2][a_c0+2][a_r0] = aR0.z; As[nb2][a_c0+3][a_r0] = aR0.w;
            As[nb2][a_c0+0][a_r1] = aR1.x; As[nb2][a_c0+1][a_r1] = aR1.y;
            As[nb2][a_c0+2][a_r1] = aR1.z; As[nb2][a_c0+3][a_r1] = aR1.w;
            *(float4*)&Bs[nb2][b_r0][b_c0] = bR0;
            *(float4*)&Bs[nb2][b_r1][b_c0] = bR1;
            __syncthreads();
        }
    }

    // epilogue: add bias, write float4
#pragma unroll
    for (int ii = 0; ii < 2; ii++)
#pragma unroll
        for (int i2 = 0; i2 < 4; i2++) {
            const int r = bm + ii * 64 + ty * 4 + i2;
#pragma unroll
            for (int jj = 0; jj < 2; jj++) {
                const int c = bn + jj * 64 + tx * 4;
                float4 o;
                o.x = acc[ii*4+i2][jj*4+0] + bias[c+0];
                o.y = acc[ii*4+i2][jj*4+1] + bias[c+1];
                o.z = acc[ii*4+i2][jj*4+2] + bias[c+2];
                o.w = acc[ii*4+i2][jj*4+3] + bias[c+3];
                *(float4*)&C[(size_t)r * N + c] = o;
            }
        }
}

// ----------------------------------------------------------------------------
// Flash-attention per (query block, head, batch). 256 threads (16x16), each
// thread owns a 4x4 fragment of the 64x64 tile. Skipped blocks write zeros.
// Dynamic smem: qsT/ksT (transposed [d][r]), vs [c][d], psT [c][r].
// ----------------------------------------------------------------------------
__global__ __launch_bounds__(256)
void attn_kernel(const float* __restrict__ G)
{
    extern __shared__ float sm[];
    float* qsT = sm;                    // [64][APITCH]  qsT[d*APITCH + r]
    float* ksT = sm + 64 * APITCH;      // [64][APITCH]  ksT[d*APITCH + c]
    float* vs  = sm + 2 * 64 * APITCH;  // [64][APITCH]  vs[c*APITCH + dc]
    float* psT = sm + 3 * 64 * APITCH;  // [64][APITCH]  psT[c*APITCH + r]
    __shared__ float kbuf[64];

    const int qb = blockIdx.x, h = blockIdx.y, b = blockIdx.z;
    const int tid = threadIdx.x;
    const int tx = tid & 15, ty = tid >> 4;

    // keep check: max |G| over this query block
    if (tid < 64) kbuf[tid] = fabsf(G[b * SEQ + qb * BLK + tid]);
    __syncthreads();
    float bmax = 0.f;
#pragma unroll
    for (int i = 0; i < 64; i++) bmax = fmaxf(bmax, kbuf[i]);

    if (bmax < 0.99f) {
        const float4 z = make_float4(0.f, 0.f, 0.f, 0.f);
#pragma unroll
        for (int i = 0; i < 4; i++) {
            int f  = tid + i * 256;
            int r  = f >> 4;
            int c4 = (f & 15) << 2;
            *(float4*)&g_attn[(size_t)(b * SEQ + qb * BLK + r) * DMODEL + h * HDIM + c4] = z;
        }
        return;
    }

    // load Q transposed, pre-scaled by 1/sqrt(hd)
#pragma unroll
    for (int i = 0; i < 4; i++) {
        int f  = tid + i * 256;
        int r  = f >> 4;
        int d4 = (f & 15) << 2;
        float4 q = *(const float4*)&g_q[(size_t)(b * SEQ + qb * BLK + r) * DMODEL + h * HDIM + d4];
        qsT[(d4+0) * APITCH + r] = q.x * 0.125f;
        qsT[(d4+1) * APITCH + r] = q.y * 0.125f;
        qsT[(d4+2) * APITCH + r] = q.z * 0.125f;
        qsT[(d4+3) * APITCH + r] = q.w * 0.125f;
    }

    float m[4], l[4], o[4][4];
#pragma unroll
    for (int i = 0; i < 4; i++) {
        m[i] = -1e30f; l[i] = 0.f;
#pragma unroll
        for (int j = 0; j < 4; j++) o[i][j] = 0.f;
    }

    for (int kb = 0; kb < NB; kb++) {
        __syncthreads();   // previous iteration's PV reads done before overwrite
#pragma unroll
        for (int i = 0; i < 4; i++) {
            int f  = tid + i * 256;
            int s  = f >> 4;
            int d4 = (f & 15) << 2;
            size_t base = (size_t)(b * SEQ + kb * BLK + s) * DMODEL + h * HDIM + d4;
            float4 kq = *(const float4*)&g_k[base];
            ksT[(d4+0) * APITCH + s] = kq.x;
            ksT[(d4+1) * APITCH + s] = kq.y;
            ksT[(d4+2) * APITCH + s] = kq.z;
            ksT[(d4+3) * APITCH + s] = kq.w;
            float4 vq = *(const float4*)&g_v[base];
            *(float4*)&vs[s * APITCH + d4] = vq;
        }
        __syncthreads();

        // scores: S = Q K^T (already scaled)
        float sc[4][4];
#pragma unroll
        for (int i = 0; i < 4; i++)
#pragma unroll
            for (int j = 0; j < 4; j++) sc[i][j] = 0.f;
#pragma unroll 8
        for (int d = 0; d < 64; d++) {
            float4 qv = *(const float4*)&qsT[d * APITCH + ty * 4];
            float4 kv = *(const float4*)&ksT[d * APITCH + tx * 4];
            float qa[4] = {qv.x, qv.y, qv.z, qv.w};
            float ka[4] = {kv.x, kv.y, kv.z, kv.w};
#pragma unroll
            for (int i = 0; i < 4; i++)
#pragma unroll
                for (int j = 0; j < 4; j++)
                    sc[i][j] = fmaf(qa[i], ka[j], sc[i][j]);
        }

        // online softmax (row stats replicated across the 16 tx threads)
        float mnew[4], alpha[4];
#pragma unroll
        for (int i = 0; i < 4; i++) {
            float mb = fmaxf(fmaxf(sc[i][0], sc[i][1]), fmaxf(sc[i][2], sc[i][3]));
#pragma unroll
            for (int off = 8; off > 0; off >>= 1)
                mb = fmaxf(mb, __shfl_xor_sync(0xffffffffu, mb, off, 16));
            mnew[i]  = fmaxf(m[i], mb);
            alpha[i] = __expf(m[i] - mnew[i]);
            m[i]     = mnew[i];
        }
#pragma unroll
        for (int i = 0; i < 4; i++) {
            float s0 = 0.f;
#pragma unroll
            for (int j = 0; j < 4; j++) {
                float p = __expf(sc[i][j] - mnew[i]);
                sc[i][j] = p;
                s0 += p;
            }
#pragma unroll
            for (int off = 8; off > 0; off >>= 1)
                s0 += __shfl_xor_sync(0xffffffffu, s0, off, 16);
            l[i] = l[i] * alpha[i] + s0;
#pragma unroll
            for (int j = 0; j < 4; j++) o[i][j] *= alpha[i];
        }

        // stash P transposed for the PV GEMM
#pragma unroll
        for (int i = 0; i < 4; i++)
#pragma unroll
            for (int j = 0; j < 4; j++)
                psT[(tx * 4 + j) * APITCH + ty * 4 + i] = sc[i][j];
        __syncthreads();

        // O += P V
#pragma unroll 8
        for (int c = 0; c < 64; c++) {
            float4 pv = *(const float4*)&psT[c * APITCH + ty * 4];
            float4 vv = *(const float4*)&vs[c * APITCH + tx * 4];
            float pa[4] = {pv.x, pv.y, pv.z, pv.w};
            float va[4] = {vv.x, vv.y, vv.z, vv.w};
#pragma unroll
            for (int i = 0; i < 4; i++)
#pragma unroll
                for (int j = 0; j < 4; j++)
                    o[i][j] = fmaf(pa[i], va[j], o[i][j]);
        }
    }

    // finalize: divide by l, write [B,S,H*hd]
#pragma unroll
    for (int i = 0; i < 4; i++) {
        float inv = 1.0f / l[i];
        float4 ov = make_float4(o[i][0] * inv, o[i][1] * inv, o[i][2] * inv, o[i][3] * inv);
        *(float4*)&g_attn[(size_t)(b * SEQ + qb * BLK + ty * 4 + i) * DMODEL + h * HDIM + tx * 4] = ov;
    }
}

// ----------------------------------------------------------------------------
extern "C" void kernel_launch(void* const* d_in, const int* in_sizes, int n_in,
                              void* d_out, int out_size)
{
    const float* x  = (const float*)d_in[0];
    const float* G  = (const float*)d_in[1];
    const float* Wq = (const float*)d_in[2];
    const float* bq = (const float*)d_in[3];
    const float* Wk = (const float*)d_in[4];
    const float* bk = (const float*)d_in[5];
    const float* Wv = (const float*)d_in[6];
    const float* bv = (const float*)d_in[7];
    const float* Wo = (const float*)d_in[8];
    const float* bo = (const float*)d_in[9];
    float* out = (float*)d_out;

    float *qp, *kp, *vp, *ap;
    cudaGetSymbolAddress((void**)&qp, g_q);
    cudaGetSymbolAddress((void**)&kp, g_k);
    cudaGetSymbolAddress((void**)&vp, g_v);
    cudaGetSymbolAddress((void**)&ap, g_attn);

    const dim3 gproj(DMODEL / 128, MROWS / 128);

    sgemm_bias128<<<gproj, 256>>>(x, Wq, bq, qp, MROWS, DMODEL, DMODEL);
    sgemm_bias128<<<gproj, 256>>>(x, Wk, bk, kp, MROWS, DMODEL, DMODEL);
    sgemm_bias128<<<gproj, 256>>>(x, Wv, bv, vp, MROWS, DMODEL, DMODEL);

    const int attn_smem = 4 * 64 * APITCH * (int)sizeof(float);  // 69632 B
    cudaFuncSetAttribute(attn_kernel, cudaFuncAttributeMaxDynamicSharedMemorySize, attn_smem);
    attn_kernel<<<dim3(NB, NHEADS, BATCH), 256, attn_smem>>>(G);

    sgemm_bias128<<<gproj, 256>>>(ap, Wo, bo, out, MROWS, DMODEL, DMODEL);
}

// round 6
// speedup vs baseline: 2.9262x; 2.9262x over previous
#include <cuda_runtime.h>
#include <math.h>
#include <stdint.h>

#define BATCH   2
#define SEQ     2048
#define DMODEL  1024
#define NHEADS  16
#define HDIM    64
#define BLK     64
#define NB      (SEQ/BLK)         // 32 query blocks per batch
#define MROWS   (BATCH*SEQ)       // 4096

// smem pitches (words), chosen for conflict-free mma fragment access
#define QPITCH  68   // qs/ps/ks pitch
#define VPITCH  72   // vs pitch

// Scratch (device globals: allocation-free, graph-capture safe)
__device__ __align__(16) float g_q[MROWS*DMODEL];
__device__ __align__(16) float g_k[MROWS*DMODEL];
__device__ __align__(16) float g_v[MROWS*DMODEL];
__device__ __align__(16) float g_attn[MROWS*DMODEL];

// ---------------------------------------------------------------------------
// TF32 helpers
// ---------------------------------------------------------------------------
__device__ __forceinline__ uint32_t f2tf32(float f) {
    uint32_t u;
    asm("cvt.rna.tf32.f32 %0, %1;" : "=r"(u) : "f"(f));
    return u;
}

// D += A*B, m16n8k8, A row-major tf32, B col-major tf32, fp32 accumulate
__device__ __forceinline__ void mma_tf32(float* d, const uint32_t* a, const uint32_t* b) {
    asm volatile(
        "mma.sync.aligned.m16n8k8.row.col.f32.tf32.tf32.f32 "
        "{%0,%1,%2,%3}, {%4,%5,%6,%7}, {%8,%9}, {%0,%1,%2,%3};"
        : "+f"(d[0]), "+f"(d[1]), "+f"(d[2]), "+f"(d[3])
        : "r"(a[0]), "r"(a[1]), "r"(a[2]), "r"(a[3]),
          "r"(b[0]), "r"(b[1]));
}

// ---------------------------------------------------------------------------
// TF32 GEMM: C[M,N] = A[M,K] @ W[K,N] + bias[N]
// 128x128 tile, 256 threads (8 warps, 2x4 warp grid, 64x32 per warp),
// k-tile 16, double-buffered.
// ---------------------------------------------------------------------------
#define APIT 20
#define BPIT 136

__global__ __launch_bounds__(256, 2)
void sgemm_tf32(const float* __restrict__ A, const float* __restrict__ W,
                const float* __restrict__ bias, float* __restrict__ C,
                int M, int N, int K)
{
    __shared__ uint32_t As[2][128 * APIT];
    __shared__ uint32_t Bs[2][16 * BPIT];

    const int tid  = threadIdx.x;
    const int lane = tid & 31;
    const int wid  = tid >> 5;
    const int gi   = lane >> 2;   // group id 0..7
    const int tg   = lane & 3;    // thread in group 0..3
    const int m0   = (wid >> 2) * 64;
    const int n0   = (wid & 3) * 32;
    const int bm   = blockIdx.y * 128;
    const int bn   = blockIdx.x * 128;

    float acc[4][4][4];
#pragma unroll
    for (int i = 0; i < 4; i++)
#pragma unroll
        for (int j = 0; j < 4; j++)
#pragma unroll
            for (int r = 0; r < 4; r++) acc[i][j][r] = 0.f;

    const int am  = tid >> 2;          // 0..63 (and +64)
    const int ak  = (tid & 3) * 4;
    const int bk  = tid >> 5;          // 0..7 (and +8)
    const int bn4 = (tid & 31) * 4;

    float4 a0v, a1v, b0v, b1v;

    // prologue: k-tile 0
    a0v = *(const float4*)&A[(size_t)(bm + am) * K + ak];
    a1v = *(const float4*)&A[(size_t)(bm + am + 64) * K + ak];
    b0v = *(const float4*)&W[(size_t)(bk) * N + bn + bn4];
    b1v = *(const float4*)&W[(size_t)(bk + 8) * N + bn + bn4];
    {
        uint32_t* d0 = &As[0][am * APIT + ak];
        d0[0]=f2tf32(a0v.x); d0[1]=f2tf32(a0v.y); d0[2]=f2tf32(a0v.z); d0[3]=f2tf32(a0v.w);
        uint32_t* d1 = &As[0][(am + 64) * APIT + ak];
        d1[0]=f2tf32(a1v.x); d1[1]=f2tf32(a1v.y); d1[2]=f2tf32(a1v.z); d1[3]=f2tf32(a1v.w);
        uint32_t* e0 = &Bs[0][bk * BPIT + bn4];
        e0[0]=f2tf32(b0v.x); e0[1]=f2tf32(b0v.y); e0[2]=f2tf32(b0v.z); e0[3]=f2tf32(b0v.w);
        uint32_t* e1 = &Bs[0][(bk + 8) * BPIT + bn4];
        e1[0]=f2tf32(b1v.x); e1[1]=f2tf32(b1v.y); e1[2]=f2tf32(b1v.z); e1[3]=f2tf32(b1v.w);
    }
    __syncthreads();

    const int nkt = K / 16;
    for (int kt = 0; kt < nkt; kt++) {
        const int buf = kt & 1;
        if (kt + 1 < nkt) {
            const int ko = (kt + 1) * 16;
            a0v = *(const float4*)&A[(size_t)(bm + am) * K + ko + ak];
            a1v = *(const float4*)&A[(size_t)(bm + am + 64) * K + ko + ak];
            b0v = *(const float4*)&W[(size_t)(ko + bk) * N + bn + bn4];
            b1v = *(const float4*)&W[(size_t)(ko + bk + 8) * N + bn + bn4];
        }
#pragma unroll
        for (int ks = 0; ks < 2; ks++) {
            uint32_t af[4][4], bf[4][2];
#pragma unroll
            for (int mf = 0; mf < 4; mf++) {
                const uint32_t* p = &As[buf][(m0 + 16*mf + gi) * APIT + 8*ks + tg];
                af[mf][0] = p[0];
                af[mf][1] = p[8 * APIT];
                af[mf][2] = p[4];
                af[mf][3] = p[8 * APIT + 4];
            }
#pragma unroll
            for (int nf = 0; nf < 4; nf++) {
                bf[nf][0] = Bs[buf][(8*ks + tg) * BPIT + n0 + 8*nf + gi];
                bf[nf][1] = Bs[buf][(8*ks + tg + 4) * BPIT + n0 + 8*nf + gi];
            }
#pragma unroll
            for (int mf = 0; mf < 4; mf++)
#pragma unroll
                for (int nf = 0; nf < 4; nf++)
                    mma_tf32(acc[mf][nf], af[mf], bf[nf]);
        }
        if (kt + 1 < nkt) {
            const int nb2 = buf ^ 1;
            uint32_t* d0 = &As[nb2][am * APIT + ak];
            d0[0]=f2tf32(a0v.x); d0[1]=f2tf32(a0v.y); d0[2]=f2tf32(a0v.z); d0[3]=f2tf32(a0v.w);
            uint32_t* d1 = &As[nb2][(am + 64) * APIT + ak];
            d1[0]=f2tf32(a1v.x); d1[1]=f2tf32(a1v.y); d1[2]=f2tf32(a1v.z); d1[3]=f2tf32(a1v.w);
            uint32_t* e0 = &Bs[nb2][bk * BPIT + bn4];
            e0[0]=f2tf32(b0v.x); e0[1]=f2tf32(b0v.y); e0[2]=f2tf32(b0v.z); e0[3]=f2tf32(b0v.w);
            uint32_t* e1 = &Bs[nb2][(bk + 8) * BPIT + bn4];
            e1[0]=f2tf32(b1v.x); e1[1]=f2tf32(b1v.y); e1[2]=f2tf32(b1v.z); e1[3]=f2tf32(b1v.w);
            __syncthreads();
        }
    }

    // epilogue: C-frag rows (gi, gi+8), cols 2*tg, 2*tg+1 per 8-col frag
#pragma unroll
    for (int mf = 0; mf < 4; mf++) {
        const int r0 = bm + m0 + 16*mf + gi;
        const int r1 = r0 + 8;
#pragma unroll
        for (int nf = 0; nf < 4; nf++) {
            const int c = bn + n0 + 8*nf + 2*tg;
            float2 bi = *(const float2*)&bias[c];
            float2 v0 = make_float2(acc[mf][nf][0] + bi.x, acc[mf][nf][1] + bi.y);
            float2 v1 = make_float2(acc[mf][nf][2] + bi.x, acc[mf][nf][3] + bi.y);
            *(float2*)&C[(size_t)r0 * N + c] = v0;
            *(float2*)&C[(size_t)r1 * N + c] = v1;
        }
    }
}

// ---------------------------------------------------------------------------
// TF32 flash attention. One CTA per (qblock, head, batch), 128 threads
// (4 warps). Warp w owns query rows 16w..16w+15 and all 64 key columns,
// so softmax state and the P tile are warp-private.
// ---------------------------------------------------------------------------
__global__ __launch_bounds__(128)
void attn_tf32(const float* __restrict__ G)
{
    extern __shared__ uint32_t sm[];
    uint32_t* qs = sm;                          // Q staging, then P (aliased)
    uint32_t* ks = sm + 64 * QPITCH;            // K [key][d]
    uint32_t* vs = sm + 2 * 64 * QPITCH;        // V [key][d]
    __shared__ float kbuf[64];

    const int qb = blockIdx.x, h = blockIdx.y, b = blockIdx.z;
    const int tid  = threadIdx.x;
    const int lane = tid & 31;
    const int w    = tid >> 5;     // warp 0..3
    const int gi   = lane >> 2;    // 0..7
    const int tg   = lane & 3;     // 0..3

    // keep check: max |G| over this query block
    if (tid < 64) kbuf[tid] = fabsf(G[b * SEQ + qb * BLK + tid]);
    __syncthreads();
    float bmax = 0.f;
#pragma unroll
    for (int i = 0; i < 64; i++) bmax = fmaxf(bmax, kbuf[i]);

    if (bmax < 0.99f) {
        const float4 z = make_float4(0.f, 0.f, 0.f, 0.f);
#pragma unroll
        for (int i = 0; i < 8; i++) {
            int f  = tid + i * 128;
            int r  = f >> 4;
            int c4 = (f & 15) << 2;
            *(float4*)&g_attn[(size_t)(b * SEQ + qb * BLK + r) * DMODEL + h * HDIM + c4] = z;
        }
        return;
    }

    // stage Q (pre-scaled by 1/sqrt(64)), converted to tf32
#pragma unroll
    for (int i = 0; i < 8; i++) {
        int f  = tid + i * 128;
        int r  = f >> 4;
        int d4 = (f & 15) << 2;
        float4 q = *(const float4*)&g_q[(size_t)(b * SEQ + qb * BLK + r) * DMODEL + h * HDIM + d4];
        uint32_t* d = &qs[r * QPITCH + d4];
        d[0] = f2tf32(q.x * 0.125f);
        d[1] = f2tf32(q.y * 0.125f);
        d[2] = f2tf32(q.z * 0.125f);
        d[3] = f2tf32(q.w * 0.125f);
    }
    __syncthreads();

    // extract Q A-fragments into registers (rows 16w+gi, 16w+gi+8)
    uint32_t qa[8][4];
#pragma unroll
    for (int k8 = 0; k8 < 8; k8++) {
        const uint32_t* p = &qs[(16*w + gi) * QPITCH + 8*k8 + tg];
        qa[k8][0] = p[0];
        qa[k8][1] = p[8 * QPITCH];
        qa[k8][2] = p[4];
        qa[k8][3] = p[8 * QPITCH + 4];
    }

    float o[8][4];
#pragma unroll
    for (int nf = 0; nf < 8; nf++)
#pragma unroll
        for (int r = 0; r < 4; r++) o[nf][r] = 0.f;
    float m0r = -1e30f, m1r = -1e30f, l0 = 0.f, l1 = 0.f;

    for (int kb = 0; kb < NB; kb++) {
        __syncthreads();   // prev QK/PV reads of ks/vs done; Q extraction done (kb=0)
        // load K, V tiles (64x64 each): 1024 float4 each side, 128 thr x 8 it
#pragma unroll
        for (int i = 0; i < 8; i++) {
            int f  = tid + i * 128;
            int r  = f >> 4;
            int d4 = (f & 15) << 2;
            size_t base = (size_t)(b * SEQ + kb * BLK + r) * DMODEL + h * HDIM + d4;
            float4 kq = *(const float4*)&g_k[base];
            uint32_t* dk = &ks[r * QPITCH + d4];
            dk[0]=f2tf32(kq.x); dk[1]=f2tf32(kq.y); dk[2]=f2tf32(kq.z); dk[3]=f2tf32(kq.w);
            float4 vq = *(const float4*)&g_v[base];
            uint32_t* dv = &vs[r * VPITCH + d4];
            dv[0]=f2tf32(vq.x); dv[1]=f2tf32(vq.y); dv[2]=f2tf32(vq.z); dv[3]=f2tf32(vq.w);
        }
        __syncthreads();

        // S = Q K^T : per warp 16 rows x 64 key cols
        float sc[8][4];
#pragma unroll
        for (int nf = 0; nf < 8; nf++) {
            sc[nf][0] = sc[nf][1] = sc[nf][2] = sc[nf][3] = 0.f;
        }
#pragma unroll
        for (int k8 = 0; k8 < 8; k8++) {
#pragma unroll
            for (int nf = 0; nf < 8; nf++) {
                uint32_t bfr[2];
                bfr[0] = ks[(8*nf + gi) * QPITCH + 8*k8 + tg];
                bfr[1] = ks[(8*nf + gi) * QPITCH + 8*k8 + 4 + tg];
                mma_tf32(sc[nf], qa[k8], bfr);
            }
        }

        // online softmax (rows r0 = 16w+gi, r1 = r0+8; quad-lane reduce)
        float mb0 = -1e30f, mb1 = -1e30f;
#pragma unroll
        for (int nf = 0; nf < 8; nf++) {
            mb0 = fmaxf(mb0, fmaxf(sc[nf][0], sc[nf][1]));
            mb1 = fmaxf(mb1, fmaxf(sc[nf][2], sc[nf][3]));
        }
        mb0 = fmaxf(mb0, __shfl_xor_sync(0xffffffffu, mb0, 1));
        mb0 = fmaxf(mb0, __shfl_xor_sync(0xffffffffu, mb0, 2));
        mb1 = fmaxf(mb1, __shfl_xor_sync(0xffffffffu, mb1, 1));
        mb1 = fmaxf(mb1, __shfl_xor_sync(0xffffffffu, mb1, 2));
        const float mn0 = fmaxf(m0r, mb0);
        const float mn1 = fmaxf(m1r, mb1);
        const float al0 = __expf(m0r - mn0);
        const float al1 = __expf(m1r - mn1);
        m0r = mn0; m1r = mn1;

        float s0 = 0.f, s1 = 0.f;
        const int pr0 = (16*w + gi) * QPITCH;
        const int pr1 = pr0 + 8 * QPITCH;
#pragma unroll
        for (int nf = 0; nf < 8; nf++) {
            float p0 = __expf(sc[nf][0] - mn0);
            float p1 = __expf(sc[nf][1] - mn0);
            float p2 = __expf(sc[nf][2] - mn1);
            float p3 = __expf(sc[nf][3] - mn1);
            s0 += p0 + p1;
            s1 += p2 + p3;
            const int c = 8*nf + 2*tg;
            uint2 u0 = make_uint2(f2tf32(p0), f2tf32(p1));
            uint2 u1 = make_uint2(f2tf32(p2), f2tf32(p3));
            *(uint2*)&qs[pr0 + c] = u0;   // qs reused as P tile (warp-private rows)
            *(uint2*)&qs[pr1 + c] = u1;
        }
        s0 += __shfl_xor_sync(0xffffffffu, s0, 1);
        s0 += __shfl_xor_sync(0xffffffffu, s0, 2);
        s1 += __shfl_xor_sync(0xffffffffu, s1, 1);
        s1 += __shfl_xor_sync(0xffffffffu, s1, 2);
        l0 = l0 * al0 + s0;
        l1 = l1 * al1 + s1;
#pragma unroll
        for (int nf = 0; nf < 8; nf++) {
            o[nf][0] *= al0; o[nf][1] *= al0;
            o[nf][2] *= al1; o[nf][3] *= al1;
        }
        __syncwarp();   // P rows are warp-private: warp-level visibility suffices

        // O += P V
#pragma unroll
        for (int k8 = 0; k8 < 8; k8++) {
            uint32_t pa[4];
            const uint32_t* pp = &qs[(16*w + gi) * QPITCH + 8*k8 + tg];
            pa[0] = pp[0];
            pa[1] = pp[8 * QPITCH];
            pa[2] = pp[4];
            pa[3] = pp[8 * QPITCH + 4];
#pragma unroll
            for (int nf = 0; nf < 8; nf++) {
                uint32_t bfr[2];
                bfr[0] = vs[(8*k8 + tg) * VPITCH + 8*nf + gi];
                bfr[1] = vs[(8*k8 + tg + 4) * VPITCH + 8*nf + gi];
                mma_tf32(o[nf], pa, bfr);
            }
        }
    }

    // finalize: divide by l, write [B,S,H*hd]
    const float inv0 = 1.0f / l0;
    const float inv1 = 1.0f / l1;
    const int r0 = 16*w + gi;
    const size_t rb0 = (size_t)(b * SEQ + qb * BLK + r0) * DMODEL + h * HDIM;
    const size_t rb1 = (size_t)(b * SEQ + qb * BLK + r0 + 8) * DMODEL + h * HDIM;
#pragma unroll
    for (int nf = 0; nf < 8; nf++) {
        const int c = 8*nf + 2*tg;
        float2 v0 = make_float2(o[nf][0] * inv0, o[nf][1] * inv0);
        float2 v1 = make_float2(o[nf][2] * inv1, o[nf][3] * inv1);
        *(float2*)&g_attn[rb0 + c] = v0;
        *(float2*)&g_attn[rb1 + c] = v1;
    }
}

// ---------------------------------------------------------------------------
extern "C" void kernel_launch(void* const* d_in, const int* in_sizes, int n_in,
                              void* d_out, int out_size)
{
    const float* x  = (const float*)d_in[0];
    const float* G  = (const float*)d_in[1];
    const float* Wq = (const float*)d_in[2];
    const float* bq = (const float*)d_in[3];
    const float* Wk = (const float*)d_in[4];
    const float* bk = (const float*)d_in[5];
    const float* Wv = (const float*)d_in[6];
    const float* bv = (const float*)d_in[7];
    const float* Wo = (const float*)d_in[8];
    const float* bo = (const float*)d_in[9];
    float* out = (float*)d_out;

    float *qp, *kp, *vp, *ap;
    cudaGetSymbolAddress((void**)&qp, g_q);
    cudaGetSymbolAddress((void**)&kp, g_k);
    cudaGetSymbolAddress((void**)&vp, g_v);
    cudaGetSymbolAddress((void**)&ap, g_attn);

    const dim3 gproj(DMODEL / 128, MROWS / 128);

    sgemm_tf32<<<gproj, 256>>>(x, Wq, bq, qp, MROWS, DMODEL, DMODEL);
    sgemm_tf32<<<gproj, 256>>>(x, Wk, bk, kp, MROWS, DMODEL, DMODEL);
    sgemm_tf32<<<gproj, 256>>>(x, Wv, bv, vp, MROWS, DMODEL, DMODEL);

    const int attn_smem = (2 * 64 * QPITCH + 64 * VPITCH) * (int)sizeof(uint32_t); // 53248 B
    cudaFuncSetAttribute(attn_tf32, cudaFuncAttributeMaxDynamicSharedMemorySize, attn_smem);
    attn_tf32<<<dim3(NB, NHEADS, BATCH), 128, attn_smem>>>(G);

    sgemm_tf32<<<gproj, 256>>>(ap, Wo, bo, out, MROWS, DMODEL, DMODEL);
}